// round 1
// baseline (speedup 1.0000x reference)
#include <cuda_runtime.h>
#include <math.h>

namespace {

constexpr int B_  = 4;
constexpr int L_  = 2048;
constexpr int H_  = 16;
constexpr int E_  = 64;
constexpr int D_  = 64;
constexpr int TILE = 64;
constexpr int NT = L_ / TILE;           // 32 key/query tiles
constexpr int RS = H_ * E_;             // 1024 floats: row stride in Q/K/V
constexpr float SCALE = 0.125f;         // 1/sqrt(64)
constexpr size_t V_ELEMS = (size_t)B_ * L_ * H_ * D_;  // 8388608
constexpr int SP = 68;                  // smem row pitch (floats), 16B-aligned

__global__ __launch_bounds__(256, 1)
void attn_fused(const float* __restrict__ Q, const float* __restrict__ K,
                const float* __restrict__ Vv, float* __restrict__ outV,
                float* __restrict__ outA)
{
    // heavy tiles (large qt) first to reduce tail imbalance
    const int qt = (NT - 1) - blockIdx.x;
    const int bh = blockIdx.y;
    const int b  = bh >> 4;
    const int h  = bh & 15;
    const int tid = threadIdx.x;
    const int tr = tid >> 4;      // 0..15
    const int tc = tid & 15;      // 0..15
    const int r0 = 4 * tr;        // this thread's 4 query rows r0..r0+3
    const int c0 = 4 * tc;        // this thread's 4 cols c0..c0+3

    __shared__ float sA[TILE * SP];   // loop1: Qs[m][e]   loop2: Ps[m][n]
    __shared__ float sB[TILE * SP];   // loop1: KsT[e][n]  loop2: Vs[n][d]

    // ---- load Q tile: Qs[m][e], coalesced float4 ----
    const float* qbase = Q + ((size_t)(b * L_ + qt * TILE) * H_ + h) * E_;
    #pragma unroll
    for (int it = 0; it < 4; ++it) {
        int idx = it * 256 + tid;
        int m  = idx >> 4;
        int e4 = (idx & 15) << 2;
        *(float4*)&sA[m * SP + e4] =
            *(const float4*)(qbase + (size_t)m * RS + e4);
    }

    float m_run[4], l_run[4];
    #pragma unroll
    for (int i = 0; i < 4; ++i) { m_run[i] = -1e30f; l_run[i] = 0.0f; }

    float* aBase = outA + ((size_t)bh * L_ + (size_t)qt * TILE) * L_;

    // =================== loop 1: scores + online stats, store raw ===================
    for (int j = 0; j <= qt; ++j) {
        __syncthreads();   // previous GEMM done before refilling sB
        const float* kbase = K + ((size_t)(b * L_ + j * TILE) * H_ + h) * E_;
        #pragma unroll
        for (int it = 0; it < 4; ++it) {
            int idx = it * 256 + tid;
            int n  = idx >> 4;
            int e4 = (idx & 15) << 2;
            float4 v = *(const float4*)(kbase + (size_t)n * RS + e4);
            sB[(e4 + 0) * SP + n] = v.x;
            sB[(e4 + 1) * SP + n] = v.y;
            sB[(e4 + 2) * SP + n] = v.z;
            sB[(e4 + 3) * SP + n] = v.w;
        }
        __syncthreads();

        float acc[4][4];
        #pragma unroll
        for (int i = 0; i < 4; ++i)
            #pragma unroll
            for (int jj = 0; jj < 4; ++jj) acc[i][jj] = 0.0f;

        #pragma unroll 16
        for (int kk = 0; kk < 64; ++kk) {
            float a0 = sA[(r0 + 0) * SP + kk];
            float a1 = sA[(r0 + 1) * SP + kk];
            float a2 = sA[(r0 + 2) * SP + kk];
            float a3 = sA[(r0 + 3) * SP + kk];
            float4 bb = *(float4*)&sB[kk * SP + c0];
            acc[0][0] += a0 * bb.x; acc[0][1] += a0 * bb.y;
            acc[0][2] += a0 * bb.z; acc[0][3] += a0 * bb.w;
            acc[1][0] += a1 * bb.x; acc[1][1] += a1 * bb.y;
            acc[1][2] += a1 * bb.z; acc[1][3] += a1 * bb.w;
            acc[2][0] += a2 * bb.x; acc[2][1] += a2 * bb.y;
            acc[2][2] += a2 * bb.z; acc[2][3] += a2 * bb.w;
            acc[3][0] += a3 * bb.x; acc[3][1] += a3 * bb.y;
            acc[3][2] += a3 * bb.z; acc[3][3] += a3 * bb.w;
        }

        const bool diag = (j == qt);
        #pragma unroll
        for (int i = 0; i < 4; ++i) {
            float s0 = acc[i][0] * SCALE;
            float s1 = acc[i][1] * SCALE;
            float s2 = acc[i][2] * SCALE;
            float s3 = acc[i][3] * SCALE;
            if (diag) {
                // mask cols strictly above the diagonal within this tile
                if (c0 + 0 > r0 + i) s0 = -1e30f;
                if (c0 + 1 > r0 + i) s1 = -1e30f;
                if (c0 + 2 > r0 + i) s2 = -1e30f;
                if (c0 + 3 > r0 + i) s3 = -1e30f;
            }
            float rmax = fmaxf(fmaxf(s0, s1), fmaxf(s2, s3));
            #pragma unroll
            for (int off = 8; off >= 1; off >>= 1)
                rmax = fmaxf(rmax, __shfl_xor_sync(0xffffffffu, rmax, off));
            float mnew = fmaxf(m_run[i], rmax);
            float rs = __expf(s0 - mnew) + __expf(s1 - mnew)
                     + __expf(s2 - mnew) + __expf(s3 - mnew);
            #pragma unroll
            for (int off = 8; off >= 1; off >>= 1)
                rs += __shfl_xor_sync(0xffffffffu, rs, off);
            l_run[i] = l_run[i] * __expf(m_run[i] - mnew) + rs;
            m_run[i] = mnew;
            // store raw scaled (masked) scores; overwritten with probs in loop 2
            *(float4*)(aBase + (size_t)(r0 + i) * L_ + j * TILE + c0) =
                make_float4(s0, s1, s2, s3);
        }
    }

    // =================== zero strictly-upper tiles of A ===================
    {
        const float4 z = make_float4(0.f, 0.f, 0.f, 0.f);
        for (int j = qt + 1; j < NT; ++j) {
            #pragma unroll
            for (int i = 0; i < 4; ++i)
                *(float4*)(aBase + (size_t)(r0 + i) * L_ + j * TILE + c0) = z;
        }
    }

    // =================== loop 2: normalize A, accumulate V = P @ values ===================
    float inv_l[4];
    #pragma unroll
    for (int i = 0; i < 4; ++i) inv_l[i] = 1.0f / l_run[i];

    float vacc[4][4];
    #pragma unroll
    for (int i = 0; i < 4; ++i)
        #pragma unroll
        for (int jj = 0; jj < 4; ++jj) vacc[i][jj] = 0.0f;

    for (int j = 0; j <= qt; ++j) {
        __syncthreads();   // previous GEMM done before refilling sA/sB
        const float* vbase = Vv + ((size_t)(b * L_ + j * TILE) * H_ + h) * D_;
        #pragma unroll
        for (int it = 0; it < 4; ++it) {
            int idx = it * 256 + tid;
            int n  = idx >> 4;
            int d4 = (idx & 15) << 2;
            *(float4*)&sB[n * SP + d4] =
                *(const float4*)(vbase + (size_t)n * RS + d4);
        }
        // read back raw scores (L2-warm), normalize, write final A, stage P in smem
        #pragma unroll
        for (int i = 0; i < 4; ++i) {
            float* arow = aBase + (size_t)(r0 + i) * L_ + j * TILE + c0;
            float4 s = *(float4*)arow;
            float4 p;
            p.x = __expf(s.x - m_run[i]) * inv_l[i];
            p.y = __expf(s.y - m_run[i]) * inv_l[i];
            p.z = __expf(s.z - m_run[i]) * inv_l[i];
            p.w = __expf(s.w - m_run[i]) * inv_l[i];
            *(float4*)arow = p;
            *(float4*)&sA[(r0 + i) * SP + c0] = p;
        }
        __syncthreads();

        #pragma unroll 16
        for (int kk = 0; kk < 64; ++kk) {
            float a0 = sA[(r0 + 0) * SP + kk];
            float a1 = sA[(r0 + 1) * SP + kk];
            float a2 = sA[(r0 + 2) * SP + kk];
            float a3 = sA[(r0 + 3) * SP + kk];
            float4 bb = *(float4*)&sB[kk * SP + c0];
            vacc[0][0] += a0 * bb.x; vacc[0][1] += a0 * bb.y;
            vacc[0][2] += a0 * bb.z; vacc[0][3] += a0 * bb.w;
            vacc[1][0] += a1 * bb.x; vacc[1][1] += a1 * bb.y;
            vacc[1][2] += a1 * bb.z; vacc[1][3] += a1 * bb.w;
            vacc[2][0] += a2 * bb.x; vacc[2][1] += a2 * bb.y;
            vacc[2][2] += a2 * bb.z; vacc[2][3] += a2 * bb.w;
            vacc[3][0] += a3 * bb.x; vacc[3][1] += a3 * bb.y;
            vacc[3][2] += a3 * bb.z; vacc[3][3] += a3 * bb.w;
        }
    }

    // ---- write V output [B, L, H, D] ----
    float* vout = outV + ((size_t)(b * L_ + qt * TILE) * H_ + h) * D_;
    #pragma unroll
    for (int i = 0; i < 4; ++i)
        *(float4*)(vout + (size_t)(r0 + i) * RS + c0) =
            make_float4(vacc[i][0], vacc[i][1], vacc[i][2], vacc[i][3]);
}

} // namespace

extern "C" void kernel_launch(void* const* d_in, const int* in_sizes, int n_in,
                              void* d_out, int out_size)
{
    const float* Q = (const float*)d_in[0];
    const float* K = (const float*)d_in[1];
    const float* V = (const float*)d_in[2];
    float* outV = (float*)d_out;
    float* outA = outV + V_ELEMS;

    dim3 grid(NT, B_ * H_);
    attn_fused<<<grid, 256>>>(Q, K, V, outV, outA);
}

// round 2
// speedup vs baseline: 1.0150x; 1.0150x over previous
#include <cuda_runtime.h>
#include <math.h>

namespace {

constexpr int B_  = 4;
constexpr int L_  = 2048;
constexpr int H_  = 16;
constexpr int E_  = 64;
constexpr int D_  = 64;
constexpr int TM  = 128;                 // query rows per CTA
constexpr int TN  = 128;                 // key cols per inner tile
constexpr int NTQ = L_ / TM;             // 16 query tiles
constexpr int RS  = H_ * E_;             // 1024 floats row stride in Q/K/V
constexpr float SCALE = 0.125f;          // 1/sqrt(64)
constexpr size_t V_ELEMS = (size_t)B_ * L_ * H_ * D_;  // 8388608

// dynamic smem layout (floats):
//  [0, 8192)        sQT [64][128] swizzled   (pass1)   | sP [128][128] (pass2)
//  [8192, 16384)    sKT [64][128] swizzled   (pass1)   | sP cont.
//  [16384, 24576)   sV  [128][64]            (pass2)
constexpr int SMEM_FLOATS = 24576;       // 96 KB

__global__ __launch_bounds__(256, 2)
void attn_fused(const float* __restrict__ Q, const float* __restrict__ K,
                const float* __restrict__ Vv, float* __restrict__ outV,
                float* __restrict__ outA)
{
    extern __shared__ float smem[];
    float* sQT = smem;                 // [64][128] (col m swizzled per e)
    float* sKT = smem + 64 * TM;       // [64][128]
    float* sP  = smem;                 // [128][128] pass2
    float* sV  = smem + TM * TN;       // [128][64]

    const int qt = (NTQ - 1) - blockIdx.x;       // heavy tiles first
    const int bh = blockIdx.y;
    const int b  = bh >> 4;
    const int h  = bh & 15;
    const int tid = threadIdx.x;
    const int tr = tid >> 4;          // 0..15
    const int tc = tid & 15;          // 0..15
    const int r0 = tr * 8;            // 8 query rows per thread
    const int c0 = tc * 8;            // 8 key cols per thread (pass1)
    const int d0 = tc * 4;            // 4 value dims per thread (pass2)

    // ---- stage Q tile (transposed + swizzled + pre-scaled), once ----
    {
        const float* qbase = Q + ((size_t)(b * L_ + qt * TM) * H_ + h) * E_;
        #pragma unroll
        for (int it = 0; it < 8; ++it) {
            int idx = it * 256 + tid;       // 0..2047
            int m  = idx >> 4;              // 0..127
            int e4 = (idx & 15) << 2;       // 0..60
            float4 v = *(const float4*)(qbase + (size_t)m * RS + e4);
            int s   = (e4 >> 2) & 7;
            int col = (((m >> 2) ^ s) << 2) | (m & 3);
            sQT[(e4 + 0) * TM + col] = v.x * SCALE;
            sQT[(e4 + 1) * TM + col] = v.y * SCALE;
            sQT[(e4 + 2) * TM + col] = v.z * SCALE;
            sQT[(e4 + 3) * TM + col] = v.w * SCALE;
        }
    }

    float m_run[8], l_run[8];
    #pragma unroll
    for (int i = 0; i < 8; ++i) { m_run[i] = -1e30f; l_run[i] = 0.0f; }

    float* aBase = outA + ((size_t)bh * L_ + (size_t)qt * TM) * L_;

    // ============ pass 1: scores + online softmax stats, store raw ============
    for (int j = 0; j <= qt; ++j) {
        __syncthreads();       // previous GEMM reads of sKT done
        const float* kbase = K + ((size_t)(b * L_ + j * TN) * H_ + h) * E_;
        #pragma unroll
        for (int it = 0; it < 8; ++it) {
            int idx = it * 256 + tid;
            int n  = idx >> 4;              // 0..127
            int e4 = (idx & 15) << 2;
            float4 v = *(const float4*)(kbase + (size_t)n * RS + e4);
            int s   = (e4 >> 2) & 7;
            int col = (((n >> 2) ^ s) << 2) | (n & 3);
            sKT[(e4 + 0) * TN + col] = v.x;
            sKT[(e4 + 1) * TN + col] = v.y;
            sKT[(e4 + 2) * TN + col] = v.z;
            sKT[(e4 + 3) * TN + col] = v.w;
        }
        __syncthreads();

        float acc[8][8];
        #pragma unroll
        for (int i = 0; i < 8; ++i)
            #pragma unroll
            for (int jj = 0; jj < 8; ++jj) acc[i][jj] = 0.0f;

        #pragma unroll 8
        for (int kk = 0; kk < 64; ++kk) {
            const float* ar = sQT + kk * TM;
            const float* br = sKT + kk * TN;
            const int s  = (kk >> 2) & 7;
            const int ga = (((r0 >> 2) ^ s) << 2);
            const int gb = (((c0 >> 2) ^ s) << 2);
            float4 a0 = *(const float4*)&ar[ga];
            float4 a1 = *(const float4*)&ar[ga ^ 4];
            float4 b0 = *(const float4*)&br[gb];
            float4 b1 = *(const float4*)&br[gb ^ 4];
            float av[8] = {a0.x, a0.y, a0.z, a0.w, a1.x, a1.y, a1.z, a1.w};
            float bv[8] = {b0.x, b0.y, b0.z, b0.w, b1.x, b1.y, b1.z, b1.w};
            #pragma unroll
            for (int i = 0; i < 8; ++i)
                #pragma unroll
                for (int jj = 0; jj < 8; ++jj)
                    acc[i][jj] += av[i] * bv[jj];
        }

        const bool diag = (j == qt);
        const int jbase = j * TN;
        #pragma unroll
        for (int i = 0; i < 8; ++i) {
            float s[8];
            #pragma unroll
            for (int jj = 0; jj < 8; ++jj) s[jj] = acc[i][jj];
            if (diag) {
                #pragma unroll
                for (int jj = 0; jj < 8; ++jj)
                    if (c0 + jj > r0 + i) s[jj] = -1e30f;
            }
            float rmax = s[0];
            #pragma unroll
            for (int jj = 1; jj < 8; ++jj) rmax = fmaxf(rmax, s[jj]);
            #pragma unroll
            for (int off = 8; off >= 1; off >>= 1)
                rmax = fmaxf(rmax, __shfl_xor_sync(0xffffffffu, rmax, off));
            float mnew = fmaxf(m_run[i], rmax);
            float rs = 0.0f;
            #pragma unroll
            for (int jj = 0; jj < 8; ++jj) rs += __expf(s[jj] - mnew);
            #pragma unroll
            for (int off = 8; off >= 1; off >>= 1)
                rs += __shfl_xor_sync(0xffffffffu, rs, off);
            l_run[i] = l_run[i] * __expf(m_run[i] - mnew) + rs;
            m_run[i] = mnew;
            float* arow = aBase + (size_t)(r0 + i) * L_ + jbase + c0;
            *(float4*)arow       = make_float4(s[0], s[1], s[2], s[3]);
            *(float4*)(arow + 4) = make_float4(s[4], s[5], s[6], s[7]);
        }
    }

    // ============ zero strictly-upper tiles of A ============
    {
        const float4 z = make_float4(0.f, 0.f, 0.f, 0.f);
        for (int j = qt + 1; j < NTQ; ++j) {
            #pragma unroll
            for (int i = 0; i < 8; ++i) {
                float* arow = aBase + (size_t)(r0 + i) * L_ + j * TN + c0;
                *(float4*)arow       = z;
                *(float4*)(arow + 4) = z;
            }
        }
    }

    // ============ pass 2: normalize A, V = P @ values ============
    float inv_l[8];
    #pragma unroll
    for (int i = 0; i < 8; ++i) inv_l[i] = 1.0f / l_run[i];

    float4 vacc[8];
    #pragma unroll
    for (int i = 0; i < 8; ++i) vacc[i] = make_float4(0.f, 0.f, 0.f, 0.f);

    for (int j = 0; j <= qt; ++j) {
        __syncthreads();       // previous GEMM reads of sP/sV done (also pass1 tail)
        const float* vbase = Vv + ((size_t)(b * L_ + j * TN) * H_ + h) * D_;
        #pragma unroll
        for (int it = 0; it < 8; ++it) {
            int idx = it * 256 + tid;
            int n  = idx >> 4;              // 0..127
            int d4 = (idx & 15) << 2;
            *(float4*)&sV[n * D_ + d4] =
                *(const float4*)(vbase + (size_t)n * RS + d4);
        }
        // read raw S back (L2-warm), normalize, write A, stage P
        #pragma unroll
        for (int i = 0; i < 8; ++i) {
            float* arow = aBase + (size_t)(r0 + i) * L_ + j * TN + c0;
            float4 s0 = *(float4*)arow;
            float4 s1 = *(float4*)(arow + 4);
            const float mi = m_run[i], il = inv_l[i];
            float4 p0, p1;
            p0.x = __expf(s0.x - mi) * il;  p0.y = __expf(s0.y - mi) * il;
            p0.z = __expf(s0.z - mi) * il;  p0.w = __expf(s0.w - mi) * il;
            p1.x = __expf(s1.x - mi) * il;  p1.y = __expf(s1.y - mi) * il;
            p1.z = __expf(s1.z - mi) * il;  p1.w = __expf(s1.w - mi) * il;
            *(float4*)arow       = p0;
            *(float4*)(arow + 4) = p1;
            *(float4*)&sP[(r0 + i) * TN + c0]     = p0;
            *(float4*)&sP[(r0 + i) * TN + c0 + 4] = p1;
        }
        __syncthreads();

        #pragma unroll 4
        for (int n = 0; n < TN; n += 4) {
            float4 v0 = *(const float4*)&sV[(n + 0) * D_ + d0];
            float4 v1 = *(const float4*)&sV[(n + 1) * D_ + d0];
            float4 v2 = *(const float4*)&sV[(n + 2) * D_ + d0];
            float4 v3 = *(const float4*)&sV[(n + 3) * D_ + d0];
            #pragma unroll
            for (int i = 0; i < 8; ++i) {
                float4 p = *(const float4*)&sP[(r0 + i) * TN + n];
                vacc[i].x += p.x * v0.x + p.y * v1.x + p.z * v2.x + p.w * v3.x;
                vacc[i].y += p.x * v0.y + p.y * v1.y + p.z * v2.y + p.w * v3.y;
                vacc[i].z += p.x * v0.z + p.y * v1.z + p.z * v2.z + p.w * v3.z;
                vacc[i].w += p.x * v0.w + p.y * v1.w + p.z * v2.w + p.w * v3.w;
            }
        }
    }

    // ---- write V output [B, L, H, D] ----
    float* vout = outV + ((size_t)(b * L_ + qt * TM) * H_ + h) * D_;
    #pragma unroll
    for (int i = 0; i < 8; ++i)
        *(float4*)(vout + (size_t)(r0 + i) * RS + d0) = vacc[i];
}

} // namespace

extern "C" void kernel_launch(void* const* d_in, const int* in_sizes, int n_in,
                              void* d_out, int out_size)
{
    const float* Q = (const float*)d_in[0];
    const float* K = (const float*)d_in[1];
    const float* V = (const float*)d_in[2];
    float* outV = (float*)d_out;
    float* outA = outV + V_ELEMS;

    cudaFuncSetAttribute(attn_fused, cudaFuncAttributeMaxDynamicSharedMemorySize,
                         SMEM_FLOATS * sizeof(float));
    dim3 grid(NTQ, B_ * H_);
    attn_fused<<<grid, 256, SMEM_FLOATS * sizeof(float)>>>(Q, K, V, outV, outA);
}

// round 3
// speedup vs baseline: 1.1378x; 1.1210x over previous
#include <cuda_runtime.h>
#include <math.h>

namespace {

constexpr int B_  = 4;
constexpr int L_  = 2048;
constexpr int H_  = 16;
constexpr int E_  = 64;
constexpr int D_  = 64;
constexpr int TM  = 128;
constexpr int TN  = 128;
constexpr int NTQ = L_ / TM;             // 16 query tiles
constexpr int RS  = H_ * E_;             // 1024
constexpr float SCALE = 0.125f;
constexpr size_t V_ELEMS = (size_t)B_ * L_ * H_ * D_;

constexpr int SMEM_FLOATS = 24576;       // 96 KB

union F2U { float2 f; unsigned long long u; };

__device__ __forceinline__ float2 ffma2(float2 a, float2 b, float2 c) {
    F2U A, Bv, C, Dv;
    A.f = a; Bv.f = b; C.f = c;
    asm("fma.rn.f32x2 %0, %1, %2, %3;"
        : "=l"(Dv.u) : "l"(A.u), "l"(Bv.u), "l"(C.u));
    return Dv.f;
}

__global__ __launch_bounds__(256, 2)
void attn_fused(const float* __restrict__ Q, const float* __restrict__ K,
                const float* __restrict__ Vv, float* __restrict__ outV,
                float* __restrict__ outA)
{
    extern __shared__ float smem[];
    float* sQT = smem;                 // [64][128] swizzled (pass1)
    float* sKT = smem + 64 * TM;       // [64][128]
    float* sP  = smem;                 // [128][128] (pass2, overlays sQT/sKT)
    float* sV  = smem + TM * TN;       // [128][64]

    const int qt = (NTQ - 1) - blockIdx.x;
    const int bh = blockIdx.y;
    const int b  = bh >> 4;
    const int h  = bh & 15;
    const int tid = threadIdx.x;
    const int tr = tid >> 4;
    const int tc = tid & 15;
    const int r0 = tr * 8;
    const int c0 = tc * 8;
    const int d0 = tc * 4;

    // ---- stage Q tile (transposed + swizzled + pre-scaled) ----
    {
        const float* qbase = Q + ((size_t)(b * L_ + qt * TM) * H_ + h) * E_;
        #pragma unroll
        for (int it = 0; it < 8; ++it) {
            int idx = it * 256 + tid;
            int m  = idx >> 4;
            int e4 = (idx & 15) << 2;
            float4 v = *(const float4*)(qbase + (size_t)m * RS + e4);
            int s   = (e4 >> 2) & 7;
            int col = (((m >> 2) ^ s) << 2) | (m & 3);
            sQT[(e4 + 0) * TM + col] = v.x * SCALE;
            sQT[(e4 + 1) * TM + col] = v.y * SCALE;
            sQT[(e4 + 2) * TM + col] = v.z * SCALE;
            sQT[(e4 + 3) * TM + col] = v.w * SCALE;
        }
    }

    float m_run[8], l_run[8];
    #pragma unroll
    for (int i = 0; i < 8; ++i) { m_run[i] = -1e30f; l_run[i] = 0.0f; }

    float* aBase = outA + ((size_t)bh * L_ + (size_t)qt * TM) * L_;

    // ============ pass 1: scores + online stats, store raw ============
    for (int j = 0; j <= qt; ++j) {
        __syncthreads();
        const float* kbase = K + ((size_t)(b * L_ + j * TN) * H_ + h) * E_;
        #pragma unroll
        for (int it = 0; it < 8; ++it) {
            int idx = it * 256 + tid;
            int n  = idx >> 4;
            int e4 = (idx & 15) << 2;
            float4 v = *(const float4*)(kbase + (size_t)n * RS + e4);
            int s   = (e4 >> 2) & 7;
            int col = (((n >> 2) ^ s) << 2) | (n & 3);
            sKT[(e4 + 0) * TN + col] = v.x;
            sKT[(e4 + 1) * TN + col] = v.y;
            sKT[(e4 + 2) * TN + col] = v.z;
            sKT[(e4 + 3) * TN + col] = v.w;
        }
        __syncthreads();

        float2 acc2[8][4];
        #pragma unroll
        for (int i = 0; i < 8; ++i)
            #pragma unroll
            for (int jj = 0; jj < 4; ++jj) acc2[i][jj] = make_float2(0.f, 0.f);

        #pragma unroll 8
        for (int kk = 0; kk < 64; ++kk) {
            const float* ar = sQT + kk * TM;
            const float* br = sKT + kk * TN;
            const int s  = (kk >> 2) & 7;
            const int ga = (((r0 >> 2) ^ s) << 2);
            const int gb = (((c0 >> 2) ^ s) << 2);
            float4 a0 = *(const float4*)&ar[ga];
            float4 a1 = *(const float4*)&ar[ga ^ 4];
            float4 b0 = *(const float4*)&br[gb];
            float4 b1 = *(const float4*)&br[gb ^ 4];
            float av[8] = {a0.x, a0.y, a0.z, a0.w, a1.x, a1.y, a1.z, a1.w};
            float2 bp[4] = {make_float2(b0.x, b0.y), make_float2(b0.z, b0.w),
                            make_float2(b1.x, b1.y), make_float2(b1.z, b1.w)};
            #pragma unroll
            for (int i = 0; i < 8; ++i) {
                float2 ad = make_float2(av[i], av[i]);
                #pragma unroll
                for (int jj = 0; jj < 4; ++jj)
                    acc2[i][jj] = ffma2(ad, bp[jj], acc2[i][jj]);
            }
        }

        const bool diag = (j == qt);
        const int jbase = j * TN;
        #pragma unroll
        for (int i = 0; i < 8; ++i) {
            float s[8];
            #pragma unroll
            for (int jj = 0; jj < 4; ++jj) {
                s[2 * jj + 0] = acc2[i][jj].x;
                s[2 * jj + 1] = acc2[i][jj].y;
            }
            if (diag) {
                #pragma unroll
                for (int jj = 0; jj < 8; ++jj)
                    if (c0 + jj > r0 + i) s[jj] = -1e30f;
            }
            float rmax = s[0];
            #pragma unroll
            for (int jj = 1; jj < 8; ++jj) rmax = fmaxf(rmax, s[jj]);
            #pragma unroll
            for (int off = 8; off >= 1; off >>= 1)
                rmax = fmaxf(rmax, __shfl_xor_sync(0xffffffffu, rmax, off));
            float mnew = fmaxf(m_run[i], rmax);
            float rs = 0.0f;
            #pragma unroll
            for (int jj = 0; jj < 8; ++jj) rs += __expf(s[jj] - mnew);
            #pragma unroll
            for (int off = 8; off >= 1; off >>= 1)
                rs += __shfl_xor_sync(0xffffffffu, rs, off);
            l_run[i] = l_run[i] * __expf(m_run[i] - mnew) + rs;
            m_run[i] = mnew;
            float* arow = aBase + (size_t)(r0 + i) * L_ + jbase + c0;
            *(float4*)arow       = make_float4(s[0], s[1], s[2], s[3]);
            *(float4*)(arow + 4) = make_float4(s[4], s[5], s[6], s[7]);
        }
    }

    // ============ zero strictly-upper tiles of A ============
    {
        const float4 z = make_float4(0.f, 0.f, 0.f, 0.f);
        for (int j = qt + 1; j < NTQ; ++j) {
            #pragma unroll
            for (int i = 0; i < 8; ++i) {
                float* arow = aBase + (size_t)(r0 + i) * L_ + j * TN + c0;
                *(float4*)arow       = z;
                *(float4*)(arow + 4) = z;
            }
        }
    }

    // ============ pass 2: normalize A, V = P @ values ============
    float inv_l[8];
    #pragma unroll
    for (int i = 0; i < 8; ++i) inv_l[i] = 1.0f / l_run[i];

    float2 vacc2[8][2];
    #pragma unroll
    for (int i = 0; i < 8; ++i) {
        vacc2[i][0] = make_float2(0.f, 0.f);
        vacc2[i][1] = make_float2(0.f, 0.f);
    }

    for (int j = 0; j <= qt; ++j) {
        __syncthreads();
        const float* vbase = Vv + ((size_t)(b * L_ + j * TN) * H_ + h) * D_;
        #pragma unroll
        for (int it = 0; it < 8; ++it) {
            int idx = it * 256 + tid;
            int n  = idx >> 4;
            int d4 = (idx & 15) << 2;
            *(float4*)&sV[n * D_ + d4] =
                *(const float4*)(vbase + (size_t)n * RS + d4);
        }
        #pragma unroll
        for (int i = 0; i < 8; ++i) {
            float* arow = aBase + (size_t)(r0 + i) * L_ + j * TN + c0;
            float4 s0 = *(float4*)arow;
            float4 s1 = *(float4*)(arow + 4);
            const float mi = m_run[i], il = inv_l[i];
            float4 p0, p1;
            p0.x = __expf(s0.x - mi) * il;  p0.y = __expf(s0.y - mi) * il;
            p0.z = __expf(s0.z - mi) * il;  p0.w = __expf(s0.w - mi) * il;
            p1.x = __expf(s1.x - mi) * il;  p1.y = __expf(s1.y - mi) * il;
            p1.z = __expf(s1.z - mi) * il;  p1.w = __expf(s1.w - mi) * il;
            *(float4*)arow       = p0;
            *(float4*)(arow + 4) = p1;
            *(float4*)&sP[(r0 + i) * TN + c0]     = p0;
            *(float4*)&sP[(r0 + i) * TN + c0 + 4] = p1;
        }
        __syncthreads();

        #pragma unroll 4
        for (int n = 0; n < TN; n += 4) {
            float4 v0 = *(const float4*)&sV[(n + 0) * D_ + d0];
            float4 v1 = *(const float4*)&sV[(n + 1) * D_ + d0];
            float4 v2 = *(const float4*)&sV[(n + 2) * D_ + d0];
            float4 v3 = *(const float4*)&sV[(n + 3) * D_ + d0];
            float2 v0a = make_float2(v0.x, v0.y), v0b = make_float2(v0.z, v0.w);
            float2 v1a = make_float2(v1.x, v1.y), v1b = make_float2(v1.z, v1.w);
            float2 v2a = make_float2(v2.x, v2.y), v2b = make_float2(v2.z, v2.w);
            float2 v3a = make_float2(v3.x, v3.y), v3b = make_float2(v3.z, v3.w);
            #pragma unroll
            for (int i = 0; i < 8; ++i) {
                float4 p = *(const float4*)&sP[(r0 + i) * TN + n];
                float2 px = make_float2(p.x, p.x);
                float2 py = make_float2(p.y, p.y);
                float2 pz = make_float2(p.z, p.z);
                float2 pw = make_float2(p.w, p.w);
                vacc2[i][0] = ffma2(px, v0a, vacc2[i][0]);
                vacc2[i][1] = ffma2(px, v0b, vacc2[i][1]);
                vacc2[i][0] = ffma2(py, v1a, vacc2[i][0]);
                vacc2[i][1] = ffma2(py, v1b, vacc2[i][1]);
                vacc2[i][0] = ffma2(pz, v2a, vacc2[i][0]);
                vacc2[i][1] = ffma2(pz, v2b, vacc2[i][1]);
                vacc2[i][0] = ffma2(pw, v3a, vacc2[i][0]);
                vacc2[i][1] = ffma2(pw, v3b, vacc2[i][1]);
            }
        }
    }

    // ---- write V output ----
    float* vout = outV + ((size_t)(b * L_ + qt * TM) * H_ + h) * D_;
    #pragma unroll
    for (int i = 0; i < 8; ++i)
        *(float4*)(vout + (size_t)(r0 + i) * RS + d0) =
            make_float4(vacc2[i][0].x, vacc2[i][0].y,
                        vacc2[i][1].x, vacc2[i][1].y);
}

} // namespace

extern "C" void kernel_launch(void* const* d_in, const int* in_sizes, int n_in,
                              void* d_out, int out_size)
{
    const float* Q = (const float*)d_in[0];
    const float* K = (const float*)d_in[1];
    const float* V = (const float*)d_in[2];
    float* outV = (float*)d_out;
    float* outA = outV + V_ELEMS;

    cudaFuncSetAttribute(attn_fused, cudaFuncAttributeMaxDynamicSharedMemorySize,
                         SMEM_FLOATS * sizeof(float));
    dim3 grid(NTQ, B_ * H_);
    attn_fused<<<grid, 256, SMEM_FLOATS * sizeof(float)>>>(Q, K, V, outV, outA);
}

// round 4
// speedup vs baseline: 1.6610x; 1.4599x over previous
#include <cuda_runtime.h>
#include <cuda_bf16.h>
#include <math.h>
#include <stdint.h>

namespace {

constexpr int B_  = 4;
constexpr int L_  = 2048;
constexpr int H_  = 16;
constexpr int E_  = 64;
constexpr int D_  = 64;
constexpr int TM  = 128;
constexpr int TN  = 128;
constexpr int NTQ = L_ / TM;            // 16
constexpr int RS  = H_ * E_;            // 1024
constexpr float SCALE = 0.125f;
constexpr size_t V_ELEMS = (size_t)B_ * L_ * H_ * D_;

// smem byte offsets (bf16 hi/lo planes)
constexpr int QH_OFF = 0;        // [128][64] bf16, 128B rows
constexpr int QL_OFF = 16384;
constexpr int KH_OFF = 32768;
constexpr int KL_OFF = 49152;
constexpr int VH_OFF = 65536;    // [seq 128][d 64]
constexpr int VL_OFF = 81920;
constexpr int PH_OFF = 98304;    // [128][128] bf16, 256B rows
constexpr int PL_OFF = 131072;
constexpr int SMEM_BYTES = 163840;   // 160 KB

__device__ __forceinline__ void ldsm4(uint32_t r[4], uint32_t a) {
    asm volatile("ldmatrix.sync.aligned.m8n8.x4.shared.b16 {%0,%1,%2,%3}, [%4];"
        : "=r"(r[0]), "=r"(r[1]), "=r"(r[2]), "=r"(r[3]) : "r"(a));
}
__device__ __forceinline__ void ldsm4t(uint32_t r[4], uint32_t a) {
    asm volatile("ldmatrix.sync.aligned.m8n8.x4.trans.shared.b16 {%0,%1,%2,%3}, [%4];"
        : "=r"(r[0]), "=r"(r[1]), "=r"(r[2]), "=r"(r[3]) : "r"(a));
}
__device__ __forceinline__ void mma_bf16(float c[4], const uint32_t a[4],
                                         uint32_t b0, uint32_t b1) {
    asm volatile(
        "mma.sync.aligned.m16n8k16.row.col.f32.bf16.bf16.f32 "
        "{%0,%1,%2,%3}, {%4,%5,%6,%7}, {%8,%9}, {%0,%1,%2,%3};"
        : "+f"(c[0]), "+f"(c[1]), "+f"(c[2]), "+f"(c[3])
        : "r"(a[0]), "r"(a[1]), "r"(a[2]), "r"(a[3]), "r"(b0), "r"(b1));
}

__device__ __forceinline__ uint32_t pack2(float x, float y) {
    uint16_t hx = __bfloat16_as_ushort(__float2bfloat16_rn(x));
    uint16_t hy = __bfloat16_as_ushort(__float2bfloat16_rn(y));
    return (uint32_t)hx | ((uint32_t)hy << 16);
}
// split x,y into bf16 hi plane + bf16 residual plane
__device__ __forceinline__ void split2(float x, float y, uint32_t& hi, uint32_t& lo) {
    __nv_bfloat16 xh = __float2bfloat16_rn(x);
    __nv_bfloat16 yh = __float2bfloat16_rn(y);
    hi = (uint32_t)__bfloat16_as_ushort(xh) | ((uint32_t)__bfloat16_as_ushort(yh) << 16);
    lo = pack2(x - __bfloat162float(xh), y - __bfloat162float(yh));
}

// stage a 128x64 fp32 tile (row stride RS) into hi/lo bf16 smem planes
// (128B rows, chunk-XOR swizzle: chunk' = chunk ^ (row&7))
__device__ __forceinline__ void stage_hl(const float* __restrict__ g,
                                         char* sm, int HOFF, int LOFF,
                                         int tid, float scale) {
    #pragma unroll
    for (int it = 0; it < 8; ++it) {
        int idx = it * 256 + tid;
        int n  = idx >> 4;
        int e4 = (idx & 15) << 2;
        float4 v = *(const float4*)(g + (size_t)n * RS + e4);
        v.x *= scale; v.y *= scale; v.z *= scale; v.w *= scale;
        uint32_t h0, l0, h1, l1;
        split2(v.x, v.y, h0, l0);
        split2(v.z, v.w, h1, l1);
        int ch  = (e4 >> 3) ^ (n & 7);
        int off = n * 128 + ch * 16 + (e4 & 4) * 2;   // (e4&7) in {0,4} -> bytes {0,8}
        *(uint2*)(sm + HOFF + off) = make_uint2(h0, h1);
        *(uint2*)(sm + LOFF + off) = make_uint2(l0, l1);
    }
}

// S = Q*K^T for this warp's 16 rows x 128 cols, 3-term bf16 split, k=64
__device__ __forceinline__ void compute_S(float acc[16][4],
                                          const uint32_t qh[4][4], const uint32_t ql[4][4],
                                          uint32_t khb, uint32_t klb, int lane) {
    #pragma unroll
    for (int nt = 0; nt < 16; ++nt) {
        const int row = nt * 8 + (lane & 7);
        const uint32_t roff = row * 128;
        uint32_t kh0[4], kh1[4], kl0[4], kl1[4];
        ldsm4(kh0, khb + roff + ((uint32_t)(((lane >> 3)    ) ^ (row & 7)) << 4));
        ldsm4(kh1, khb + roff + ((uint32_t)((4 + (lane >> 3)) ^ (row & 7)) << 4));
        ldsm4(kl0, klb + roff + ((uint32_t)(((lane >> 3)    ) ^ (row & 7)) << 4));
        ldsm4(kl1, klb + roff + ((uint32_t)((4 + (lane >> 3)) ^ (row & 7)) << 4));
        float* c = acc[nt];
        mma_bf16(c, qh[0], kh0[0], kh0[1]);
        mma_bf16(c, qh[1], kh0[2], kh0[3]);
        mma_bf16(c, qh[2], kh1[0], kh1[1]);
        mma_bf16(c, qh[3], kh1[2], kh1[3]);
        mma_bf16(c, ql[0], kh0[0], kh0[1]);
        mma_bf16(c, ql[1], kh0[2], kh0[3]);
        mma_bf16(c, ql[2], kh1[0], kh1[1]);
        mma_bf16(c, ql[3], kh1[2], kh1[3]);
        mma_bf16(c, qh[0], kl0[0], kl0[1]);
        mma_bf16(c, qh[1], kl0[2], kl0[3]);
        mma_bf16(c, qh[2], kl1[0], kl1[1]);
        mma_bf16(c, qh[3], kl1[2], kl1[3]);
    }
}

__device__ __forceinline__ void mask_diag(float acc[16][4], int jTN,
                                          int grow0, int grow1, int cq) {
    #pragma unroll
    for (int nt = 0; nt < 16; ++nt) {
        int c0g = jTN + nt * 8 + cq;
        if (c0g     > grow0) acc[nt][0] = -1e30f;
        if (c0g + 1 > grow0) acc[nt][1] = -1e30f;
        if (c0g     > grow1) acc[nt][2] = -1e30f;
        if (c0g + 1 > grow1) acc[nt][3] = -1e30f;
    }
}

__global__ void __launch_bounds__(256, 1)
attn_mma(const float* __restrict__ Q, const float* __restrict__ K,
         const float* __restrict__ Vv, float* __restrict__ outV,
         float* __restrict__ outA)
{
    extern __shared__ char sm[];
    const int qt  = (NTQ - 1) - blockIdx.x;     // heavy tiles first
    const int bh  = blockIdx.y;
    const int b   = bh >> 4;
    const int h   = bh & 15;
    const int tid = threadIdx.x;
    const int wid = tid >> 5;
    const int lane = tid & 31;
    const int m0  = wid * 16;                    // this warp's query rows
    const int rq  = lane >> 2;                   // 0..7
    const int cq  = (lane & 3) * 2;

    const uint32_t smb = (uint32_t)__cvta_generic_to_shared(sm);

    // ---- stage Q (pre-scaled) once ----
    stage_hl(Q + ((size_t)(b * L_ + qt * TM) * H_ + h) * E_, sm, QH_OFF, QL_OFF, tid, SCALE);
    __syncthreads();

    // ---- Q fragments (persistent) ----
    uint32_t qh[4][4], ql[4][4];
    #pragma unroll
    for (int ks = 0; ks < 4; ++ks) {
        int row = m0 + (lane & 7) + ((lane >> 3) & 1) * 8;
        int ch  = 2 * ks + (lane >> 4);
        uint32_t off = row * 128 + ((uint32_t)(ch ^ (row & 7)) << 4);
        ldsm4(qh[ks], smb + QH_OFF + off);
        ldsm4(ql[ks], smb + QL_OFF + off);
    }

    const int grow0 = qt * TM + m0 + rq;
    const int grow1 = grow0 + 8;

    float m_run[2] = {-1e30f, -1e30f};
    float l_run[2] = {0.0f, 0.0f};

    // =================== pass 1: stats only, no global writes ===================
    for (int j = 0; j <= qt; ++j) {
        __syncthreads();
        stage_hl(K + ((size_t)(b * L_ + j * TN) * H_ + h) * E_, sm, KH_OFF, KL_OFF, tid, 1.0f);
        __syncthreads();

        float acc[16][4];
        #pragma unroll
        for (int nt = 0; nt < 16; ++nt)
            #pragma unroll
            for (int e = 0; e < 4; ++e) acc[nt][e] = 0.0f;

        compute_S(acc, qh, ql, smb + KH_OFF, smb + KL_OFF, lane);
        if (j == qt) mask_diag(acc, j * TN, grow0, grow1, cq);

        float mx0 = -1e30f, mx1 = -1e30f;
        #pragma unroll
        for (int nt = 0; nt < 16; ++nt) {
            mx0 = fmaxf(mx0, fmaxf(acc[nt][0], acc[nt][1]));
            mx1 = fmaxf(mx1, fmaxf(acc[nt][2], acc[nt][3]));
        }
        mx0 = fmaxf(mx0, __shfl_xor_sync(0xffffffffu, mx0, 1));
        mx0 = fmaxf(mx0, __shfl_xor_sync(0xffffffffu, mx0, 2));
        mx1 = fmaxf(mx1, __shfl_xor_sync(0xffffffffu, mx1, 1));
        mx1 = fmaxf(mx1, __shfl_xor_sync(0xffffffffu, mx1, 2));
        float mn0 = fmaxf(m_run[0], mx0);
        float mn1 = fmaxf(m_run[1], mx1);
        float s0 = 0.0f, s1 = 0.0f;
        #pragma unroll
        for (int nt = 0; nt < 16; ++nt) {
            s0 += __expf(acc[nt][0] - mn0) + __expf(acc[nt][1] - mn0);
            s1 += __expf(acc[nt][2] - mn1) + __expf(acc[nt][3] - mn1);
        }
        s0 += __shfl_xor_sync(0xffffffffu, s0, 1);
        s0 += __shfl_xor_sync(0xffffffffu, s0, 2);
        s1 += __shfl_xor_sync(0xffffffffu, s1, 1);
        s1 += __shfl_xor_sync(0xffffffffu, s1, 2);
        l_run[0] = l_run[0] * __expf(m_run[0] - mn0) + s0;  m_run[0] = mn0;
        l_run[1] = l_run[1] * __expf(m_run[1] - mn1) + s1;  m_run[1] = mn1;
    }
    const float inv_l0 = 1.0f / l_run[0];
    const float inv_l1 = 1.0f / l_run[1];

    // =================== zero strictly-upper tiles of A ===================
    float* aBase = outA + ((size_t)bh * L_ + (size_t)qt * TM) * L_;
    for (int j = qt + 1; j < NTQ; ++j) {
        #pragma unroll
        for (int it = 0; it < 16; ++it) {
            int idx = it * 256 + tid;          // 0..4095
            int r   = idx >> 5;                // 0..127
            int c4  = (idx & 31) << 2;         // 0..124
            *(float4*)(aBase + (size_t)r * L_ + j * TN + c4) = make_float4(0.f, 0.f, 0.f, 0.f);
        }
    }

    // =================== pass 2: recompute, write A once, PV ===================
    float o[8][4];
    #pragma unroll
    for (int dt = 0; dt < 8; ++dt)
        #pragma unroll
        for (int e = 0; e < 4; ++e) o[dt][e] = 0.0f;

    for (int j = 0; j <= qt; ++j) {
        __syncthreads();
        stage_hl(K  + ((size_t)(b * L_ + j * TN) * H_ + h) * E_, sm, KH_OFF, KL_OFF, tid, 1.0f);
        stage_hl(Vv + ((size_t)(b * L_ + j * TN) * H_ + h) * D_, sm, VH_OFF, VL_OFF, tid, 1.0f);
        __syncthreads();

        float acc[16][4];
        #pragma unroll
        for (int nt = 0; nt < 16; ++nt)
            #pragma unroll
            for (int e = 0; e < 4; ++e) acc[nt][e] = 0.0f;

        compute_S(acc, qh, ql, smb + KH_OFF, smb + KL_OFF, lane);
        if (j == qt) mask_diag(acc, j * TN, grow0, grow1, cq);

        // normalize -> write A (fp32) + stage P (bf16 hi/lo) for this warp's rows
        const int r_lo = m0 + rq;
        #pragma unroll
        for (int nt = 0; nt < 16; ++nt) {
            float p00 = __expf(acc[nt][0] - m_run[0]) * inv_l0;
            float p01 = __expf(acc[nt][1] - m_run[0]) * inv_l0;
            float p10 = __expf(acc[nt][2] - m_run[1]) * inv_l1;
            float p11 = __expf(acc[nt][3] - m_run[1]) * inv_l1;
            int c = nt * 8 + cq;
            float* a0p = aBase + (size_t)r_lo * L_ + j * TN + c;
            *(float2*)a0p            = make_float2(p00, p01);
            *(float2*)(a0p + 8 * L_) = make_float2(p10, p11);
            // smem P: 256B rows, chunk' = (ch&8)|((ch^row)&7)
            uint32_t hi, lo;
            int ch  = c >> 3;
            {
                int row = r_lo;
                int chs = (ch & 8) | ((ch ^ row) & 7);
                int off = row * 256 + chs * 16 + (c & 7) * 2;
                split2(p00, p01, hi, lo);
                *(uint32_t*)(sm + PH_OFF + off) = hi;
                *(uint32_t*)(sm + PL_OFF + off) = lo;
            }
            {
                int row = r_lo + 8;
                int chs = (ch & 8) | ((ch ^ row) & 7);
                int off = row * 256 + chs * 16 + (c & 7) * 2;
                split2(p10, p11, hi, lo);
                *(uint32_t*)(sm + PH_OFF + off) = hi;
                *(uint32_t*)(sm + PL_OFF + off) = lo;
            }
        }
        __syncwarp();   // warp reads only its own P rows

        // P fragments for all 8 k-steps (k = key dim 128)
        uint32_t ph[8][4], pl[8][4];
        #pragma unroll
        for (int ks = 0; ks < 8; ++ks) {
            int row = m0 + (lane & 7) + ((lane >> 3) & 1) * 8;
            int ch  = 2 * ks + (lane >> 4);
            int chs = (ch & 8) | ((ch ^ row) & 7);
            uint32_t off = row * 256 + (chs << 4);
            ldsm4(ph[ks], smb + PH_OFF + off);
            ldsm4(pl[ks], smb + PL_OFF + off);
        }

        // O += P @ V  (V via ldmatrix.trans from [seq][d])
        #pragma unroll
        for (int dt = 0; dt < 8; ++dt) {
            const int dch = dt;     // 16B chunk index along d
            #pragma unroll
            for (int q4 = 0; q4 < 4; ++q4) {
                int row = q4 * 32 + lane;
                uint32_t off = row * 128 + ((uint32_t)(dch ^ (row & 7)) << 4);
                uint32_t vh[4], vl[4];
                ldsm4t(vh, smb + VH_OFF + off);
                ldsm4t(vl, smb + VL_OFF + off);
                mma_bf16(o[dt], ph[2 * q4],     vh[0], vh[1]);
                mma_bf16(o[dt], ph[2 * q4 + 1], vh[2], vh[3]);
                mma_bf16(o[dt], ph[2 * q4],     vl[0], vl[1]);
                mma_bf16(o[dt], ph[2 * q4 + 1], vl[2], vl[3]);
                mma_bf16(o[dt], pl[2 * q4],     vh[0], vh[1]);
                mma_bf16(o[dt], pl[2 * q4 + 1], vh[2], vh[3]);
            }
        }
    }

    // ---- write V output [B, L, H, D] ----
    float* vout = outV + ((size_t)(b * L_ + qt * TM) * H_ + h) * D_;
    #pragma unroll
    for (int dt = 0; dt < 8; ++dt) {
        int d = dt * 8 + cq;
        float* p0 = vout + (size_t)(m0 + rq) * RS + d;
        *(float2*)p0            = make_float2(o[dt][0], o[dt][1]);
        *(float2*)(p0 + 8 * RS) = make_float2(o[dt][2], o[dt][3]);
    }
}

} // namespace

extern "C" void kernel_launch(void* const* d_in, const int* in_sizes, int n_in,
                              void* d_out, int out_size)
{
    const float* Q = (const float*)d_in[0];
    const float* K = (const float*)d_in[1];
    const float* V = (const float*)d_in[2];
    float* outV = (float*)d_out;
    float* outA = outV + V_ELEMS;

    cudaFuncSetAttribute(attn_mma, cudaFuncAttributeMaxDynamicSharedMemorySize, SMEM_BYTES);
    dim3 grid(NTQ, B_ * H_);
    attn_mma<<<grid, 256, SMEM_BYTES>>>(Q, K, V, outV, outA);
}

// round 6
// speedup vs baseline: 1.8040x; 1.0861x over previous
#include <cuda_runtime.h>
#include <cuda_bf16.h>
#include <math.h>
#include <stdint.h>

namespace {

constexpr int B_  = 4;
constexpr int L_  = 2048;
constexpr int H_  = 16;
constexpr int E_  = 64;
constexpr int D_  = 64;
constexpr int TM  = 128;
constexpr int TN  = 128;
constexpr int NTQ = L_ / TM;            // 16
constexpr int RS  = H_ * E_;            // 1024
constexpr float QSCALE = 0.125f * 1.4426950408889634f;   // 1/sqrt(64) * log2(e)
constexpr size_t V_ELEMS = (size_t)B_ * L_ * H_ * D_;

// smem byte offsets
constexpr int QH_OFF = 0;        // [128][64] bf16 planes, 128B rows, XOR swizzle
constexpr int QL_OFF = 16384;
constexpr int KH_OFF = 32768;
constexpr int KL_OFF = 49152;
constexpr int VH_OFF = 65536;
constexpr int VL_OFF = 81920;
constexpr int FK_OFF = 98304;    // fp32 staging K tile [128][64]
constexpr int FV_OFF = 131072;   // fp32 staging V tile
constexpr int SMEM_BYTES = 163840;   // 160 KB

__device__ __forceinline__ void ldsm4(uint32_t r[4], uint32_t a) {
    asm volatile("ldmatrix.sync.aligned.m8n8.x4.shared.b16 {%0,%1,%2,%3}, [%4];"
        : "=r"(r[0]), "=r"(r[1]), "=r"(r[2]), "=r"(r[3]) : "r"(a));
}
__device__ __forceinline__ void ldsm4t(uint32_t r[4], uint32_t a) {
    asm volatile("ldmatrix.sync.aligned.m8n8.x4.trans.shared.b16 {%0,%1,%2,%3}, [%4];"
        : "=r"(r[0]), "=r"(r[1]), "=r"(r[2]), "=r"(r[3]) : "r"(a));
}
__device__ __forceinline__ void mma_bf16(float c[4], const uint32_t a[4],
                                         uint32_t b0, uint32_t b1) {
    asm volatile(
        "mma.sync.aligned.m16n8k16.row.col.f32.bf16.bf16.f32 "
        "{%0,%1,%2,%3}, {%4,%5,%6,%7}, {%8,%9}, {%0,%1,%2,%3};"
        : "+f"(c[0]), "+f"(c[1]), "+f"(c[2]), "+f"(c[3])
        : "r"(a[0]), "r"(a[1]), "r"(a[2]), "r"(a[3]), "r"(b0), "r"(b1));
}
__device__ __forceinline__ float ex2(float x) {
    float y;
    asm("ex2.approx.ftz.f32 %0, %1;" : "=f"(y) : "f"(x));
    return y;
}
__device__ __forceinline__ void cp16(uint32_t dst, const void* src) {
    asm volatile("cp.async.cg.shared.global [%0], [%1], 16;" :: "r"(dst), "l"(src));
}
__device__ __forceinline__ void cp_commit() {
    asm volatile("cp.async.commit_group;");
}
template <int N>
__device__ __forceinline__ void cp_wait() {
    asm volatile("cp.async.wait_group %0;" :: "n"(N));
}

__device__ __forceinline__ uint32_t pack2(float x, float y) {
    uint16_t hx = __bfloat16_as_ushort(__float2bfloat16_rn(x));
    uint16_t hy = __bfloat16_as_ushort(__float2bfloat16_rn(y));
    return (uint32_t)hx | ((uint32_t)hy << 16);
}
__device__ __forceinline__ void split2(float x, float y, uint32_t& hi, uint32_t& lo) {
    __nv_bfloat16 xh = __float2bfloat16_rn(x);
    __nv_bfloat16 yh = __float2bfloat16_rn(y);
    hi = (uint32_t)__bfloat16_as_ushort(xh) | ((uint32_t)__bfloat16_as_ushort(yh) << 16);
    lo = pack2(x - __bfloat162float(xh), y - __bfloat162float(yh));
}

// stage 128x64 fp32 tile from GLOBAL into hi/lo bf16 planes (for Q only)
__device__ __forceinline__ void stage_hl(const float* __restrict__ g,
                                         char* sm, int HOFF, int LOFF,
                                         int tid, float scale) {
    #pragma unroll
    for (int it = 0; it < 8; ++it) {
        int idx = it * 256 + tid;
        int n  = idx >> 4;
        int e4 = (idx & 15) << 2;
        float4 v = *(const float4*)(g + (size_t)n * RS + e4);
        v.x *= scale; v.y *= scale; v.z *= scale; v.w *= scale;
        uint32_t h0, l0, h1, l1;
        split2(v.x, v.y, h0, l0);
        split2(v.z, v.w, h1, l1);
        int ch  = (e4 >> 3) ^ (n & 7);
        int off = n * 128 + ch * 16 + (e4 & 4) * 2;
        *(uint2*)(sm + HOFF + off) = make_uint2(h0, h1);
        *(uint2*)(sm + LOFF + off) = make_uint2(l0, l1);
    }
}

// async prefetch: global fp32 tile -> smem staging buffer
__device__ __forceinline__ void prefetch_tile(const float* __restrict__ g,
                                              uint32_t dstb, int tid) {
    #pragma unroll
    for (int it = 0; it < 8; ++it) {
        int idx = it * 256 + tid;
        int n  = idx >> 4;
        int e4 = (idx & 15) << 2;
        cp16(dstb + (uint32_t)(n * 256 + e4 * 4), g + (size_t)n * RS + e4);
    }
}

// convert fp32 staging -> hi + lo planes
__device__ __forceinline__ void convert_hl(const char* src, char* sm,
                                           int HOFF, int LOFF, int tid) {
    const float* f = (const float*)src;
    #pragma unroll
    for (int it = 0; it < 8; ++it) {
        int idx = it * 256 + tid;
        int n  = idx >> 4;
        int e4 = (idx & 15) << 2;
        float4 v = *(const float4*)(f + n * 64 + e4);
        uint32_t h0, l0, h1, l1;
        split2(v.x, v.y, h0, l0);
        split2(v.z, v.w, h1, l1);
        int ch  = (e4 >> 3) ^ (n & 7);
        int off = n * 128 + ch * 16 + (e4 & 4) * 2;
        *(uint2*)(sm + HOFF + off) = make_uint2(h0, h1);
        *(uint2*)(sm + LOFF + off) = make_uint2(l0, l1);
    }
}

// 3-term split S — MUST be the unique score function for both passes
// (pass-1 (m,l) and pass-2 normalization need bitwise-identical scores)
__device__ __forceinline__ void compute_S3(float acc[16][4],
                                           const uint32_t qh[4][4], const uint32_t ql[4][4],
                                           uint32_t khb, uint32_t klb, int lane) {
    #pragma unroll
    for (int nt = 0; nt < 16; ++nt) {
        const int row = nt * 8 + (lane & 7);
        const uint32_t roff = row * 128;
        uint32_t kh0[4], kh1[4], kl0[4], kl1[4];
        ldsm4(kh0, khb + roff + ((uint32_t)(((lane >> 3)    ) ^ (row & 7)) << 4));
        ldsm4(kh1, khb + roff + ((uint32_t)((4 + (lane >> 3)) ^ (row & 7)) << 4));
        ldsm4(kl0, klb + roff + ((uint32_t)(((lane >> 3)    ) ^ (row & 7)) << 4));
        ldsm4(kl1, klb + roff + ((uint32_t)((4 + (lane >> 3)) ^ (row & 7)) << 4));
        float* c = acc[nt];
        mma_bf16(c, qh[0], kh0[0], kh0[1]);
        mma_bf16(c, qh[1], kh0[2], kh0[3]);
        mma_bf16(c, qh[2], kh1[0], kh1[1]);
        mma_bf16(c, qh[3], kh1[2], kh1[3]);
        mma_bf16(c, ql[0], kh0[0], kh0[1]);
        mma_bf16(c, ql[1], kh0[2], kh0[3]);
        mma_bf16(c, ql[2], kh1[0], kh1[1]);
        mma_bf16(c, ql[3], kh1[2], kh1[3]);
        mma_bf16(c, qh[0], kl0[0], kl0[1]);
        mma_bf16(c, qh[1], kl0[2], kl0[3]);
        mma_bf16(c, qh[2], kl1[0], kl1[1]);
        mma_bf16(c, qh[3], kl1[2], kl1[3]);
    }
}

__device__ __forceinline__ void mask_diag(float acc[16][4], int jTN,
                                          int grow0, int grow1, int cq) {
    #pragma unroll
    for (int nt = 0; nt < 16; ++nt) {
        int c0g = jTN + nt * 8 + cq;
        if (c0g     > grow0) acc[nt][0] = -1e30f;
        if (c0g + 1 > grow0) acc[nt][1] = -1e30f;
        if (c0g     > grow1) acc[nt][2] = -1e30f;
        if (c0g + 1 > grow1) acc[nt][3] = -1e30f;
    }
}

__global__ void __launch_bounds__(256, 1)
attn_mma(const float* __restrict__ Q, const float* __restrict__ K,
         const float* __restrict__ Vv, float* __restrict__ outV,
         float* __restrict__ outA)
{
    extern __shared__ char sm[];
    const int qt  = (NTQ - 1) - blockIdx.x;     // heavy tiles first
    const int bh  = blockIdx.y;
    const int b   = bh >> 4;
    const int h   = bh & 15;
    const int tid = threadIdx.x;
    const int wid = tid >> 5;
    const int lane = tid & 31;
    const int m0  = wid * 16;
    const int rq  = lane >> 2;
    const int cq  = (lane & 3) * 2;

    const uint32_t smb = (uint32_t)__cvta_generic_to_shared(sm);
    const float* Kbase = K  + ((size_t)(b * L_) * H_ + h) * E_;
    const float* Vbase = Vv + ((size_t)(b * L_) * H_ + h) * D_;

    // stage Q (pre-scaled into log2 domain), kick K tile-0 prefetch
    stage_hl(Q + ((size_t)(b * L_ + qt * TM) * H_ + h) * E_, sm, QH_OFF, QL_OFF, tid, QSCALE);
    prefetch_tile(Kbase, smb + FK_OFF, tid);
    cp_commit();
    __syncthreads();

    // persistent Q fragments (hi + lo)
    uint32_t qh[4][4], ql[4][4];
    #pragma unroll
    for (int ks = 0; ks < 4; ++ks) {
        int row = m0 + (lane & 7) + ((lane >> 3) & 1) * 8;
        int ch  = 2 * ks + (lane >> 4);
        uint32_t off = row * 128 + ((uint32_t)(ch ^ (row & 7)) << 4);
        ldsm4(qh[ks], smb + QH_OFF + off);
        ldsm4(ql[ks], smb + QL_OFF + off);
    }

    const int grow0 = qt * TM + m0 + rq;
    const int grow1 = grow0 + 8;

    float m_run[2] = {-1e30f, -1e30f};
    float l_run[2] = {0.0f, 0.0f};

    // =================== pass 1: stats only (3-term, identical to pass 2) ===================
    for (int j = 0; j <= qt; ++j) {
        cp_wait<0>();
        __syncthreads();                      // staging arrived; KH/KL free
        convert_hl(sm + FK_OFF, sm, KH_OFF, KL_OFF, tid);
        __syncthreads();                      // KH/KL ready; staging free
        if (j < qt) {
            prefetch_tile(Kbase + (size_t)(j + 1) * TN * RS, smb + FK_OFF, tid);
            cp_commit();
        }

        float acc[16][4];
        #pragma unroll
        for (int nt = 0; nt < 16; ++nt)
            #pragma unroll
            for (int e = 0; e < 4; ++e) acc[nt][e] = 0.0f;

        compute_S3(acc, qh, ql, smb + KH_OFF, smb + KL_OFF, lane);
        if (j == qt) mask_diag(acc, j * TN, grow0, grow1, cq);

        float mx0 = -1e30f, mx1 = -1e30f;
        #pragma unroll
        for (int nt = 0; nt < 16; ++nt) {
            mx0 = fmaxf(mx0, fmaxf(acc[nt][0], acc[nt][1]));
            mx1 = fmaxf(mx1, fmaxf(acc[nt][2], acc[nt][3]));
        }
        mx0 = fmaxf(mx0, __shfl_xor_sync(0xffffffffu, mx0, 1));
        mx0 = fmaxf(mx0, __shfl_xor_sync(0xffffffffu, mx0, 2));
        mx1 = fmaxf(mx1, __shfl_xor_sync(0xffffffffu, mx1, 1));
        mx1 = fmaxf(mx1, __shfl_xor_sync(0xffffffffu, mx1, 2));
        float mn0 = fmaxf(m_run[0], mx0);
        float mn1 = fmaxf(m_run[1], mx1);
        float s0 = 0.0f, s1 = 0.0f;
        #pragma unroll
        for (int nt = 0; nt < 16; ++nt) {
            s0 += ex2(acc[nt][0] - mn0) + ex2(acc[nt][1] - mn0);
            s1 += ex2(acc[nt][2] - mn1) + ex2(acc[nt][3] - mn1);
        }
        s0 += __shfl_xor_sync(0xffffffffu, s0, 1);
        s0 += __shfl_xor_sync(0xffffffffu, s0, 2);
        s1 += __shfl_xor_sync(0xffffffffu, s1, 1);
        s1 += __shfl_xor_sync(0xffffffffu, s1, 2);
        l_run[0] = l_run[0] * ex2(m_run[0] - mn0) + s0;  m_run[0] = mn0;
        l_run[1] = l_run[1] * ex2(m_run[1] - mn1) + s1;  m_run[1] = mn1;
    }
    const float inv_l0 = 1.0f / l_run[0];
    const float inv_l1 = 1.0f / l_run[1];

    // prefetch pass-2 tile 0 (K and V) — overlaps with zero-fill below
    prefetch_tile(Kbase, smb + FK_OFF, tid);
    prefetch_tile(Vbase, smb + FV_OFF, tid);
    cp_commit();

    // =================== zero strictly-upper tiles of A ===================
    float* aBase = outA + ((size_t)bh * L_ + (size_t)qt * TM) * L_;
    for (int j = qt + 1; j < NTQ; ++j) {
        #pragma unroll
        for (int it = 0; it < 16; ++it) {
            int idx = it * 256 + tid;
            int r   = idx >> 5;
            int c4  = (idx & 31) << 2;
            *(float4*)(aBase + (size_t)r * L_ + j * TN + c4) = make_float4(0.f, 0.f, 0.f, 0.f);
        }
    }

    // =================== pass 2: recompute (3-term), write A, PV ===================
    float o[8][4];
    #pragma unroll
    for (int dt = 0; dt < 8; ++dt)
        #pragma unroll
        for (int e = 0; e < 4; ++e) o[dt][e] = 0.0f;

    for (int j = 0; j <= qt; ++j) {
        cp_wait<0>();
        __syncthreads();
        convert_hl(sm + FK_OFF, sm, KH_OFF, KL_OFF, tid);
        convert_hl(sm + FV_OFF, sm, VH_OFF, VL_OFF, tid);
        __syncthreads();
        if (j < qt) {
            prefetch_tile(Kbase + (size_t)(j + 1) * TN * RS, smb + FK_OFF, tid);
            prefetch_tile(Vbase + (size_t)(j + 1) * TN * RS, smb + FV_OFF, tid);
            cp_commit();
        }

        float acc[16][4];
        #pragma unroll
        for (int nt = 0; nt < 16; ++nt)
            #pragma unroll
            for (int e = 0; e < 4; ++e) acc[nt][e] = 0.0f;

        compute_S3(acc, qh, ql, smb + KH_OFF, smb + KL_OFF, lane);
        if (j == qt) mask_diag(acc, j * TN, grow0, grow1, cq);

        // fused per-quarter: normalize -> write A -> split -> PV MMAs
        // (P fragments live only 16 regs at a time)
        const int r_lo = m0 + rq;
        #pragma unroll
        for (int q4 = 0; q4 < 4; ++q4) {
            uint32_t ph[2][4], pl[2][4];
            #pragma unroll
            for (int t = 0; t < 4; ++t) {
                const int nt = 4 * q4 + t;
                float p00 = ex2(acc[nt][0] - m_run[0]) * inv_l0;
                float p01 = ex2(acc[nt][1] - m_run[0]) * inv_l0;
                float p10 = ex2(acc[nt][2] - m_run[1]) * inv_l1;
                float p11 = ex2(acc[nt][3] - m_run[1]) * inv_l1;
                int c = nt * 8 + cq;
                float* a0p = aBase + (size_t)r_lo * L_ + j * TN + c;
                *(float2*)a0p            = make_float2(p00, p01);
                *(float2*)(a0p + 8 * L_) = make_float2(p10, p11);
                const int kc = t >> 1;
                const int hf = (t & 1) * 2;
                split2(p00, p01, ph[kc][hf],     pl[kc][hf]);
                split2(p10, p11, ph[kc][hf + 1], pl[kc][hf + 1]);
            }
            const int row = q4 * 32 + lane;
            #pragma unroll
            for (int dt = 0; dt < 8; ++dt) {
                uint32_t off = row * 128 + ((uint32_t)(dt ^ (row & 7)) << 4);
                uint32_t vh[4], vl[4];
                ldsm4t(vh, smb + VH_OFF + off);
                ldsm4t(vl, smb + VL_OFF + off);
                mma_bf16(o[dt], ph[0], vh[0], vh[1]);
                mma_bf16(o[dt], ph[1], vh[2], vh[3]);
                mma_bf16(o[dt], ph[0], vl[0], vl[1]);
                mma_bf16(o[dt], ph[1], vl[2], vl[3]);
                mma_bf16(o[dt], pl[0], vh[0], vh[1]);
                mma_bf16(o[dt], pl[1], vh[2], vh[3]);
            }
        }
    }

    // ---- write V output [B, L, H, D] ----
    float* vout = outV + ((size_t)(b * L_ + qt * TM) * H_ + h) * D_;
    #pragma unroll
    for (int dt = 0; dt < 8; ++dt) {
        int d = dt * 8 + cq;
        float* p0 = vout + (size_t)(m0 + rq) * RS + d;
        *(float2*)p0            = make_float2(o[dt][0], o[dt][1]);
        *(float2*)(p0 + 8 * RS) = make_float2(o[dt][2], o[dt][3]);
    }
}

} // namespace

extern "C" void kernel_launch(void* const* d_in, const int* in_sizes, int n_in,
                              void* d_out, int out_size)
{
    const float* Q = (const float*)d_in[0];
    const float* K = (const float*)d_in[1];
    const float* V = (const float*)d_in[2];
    float* outV = (float*)d_out;
    float* outA = outV + V_ELEMS;

    cudaFuncSetAttribute(attn_mma, cudaFuncAttributeMaxDynamicSharedMemorySize, SMEM_BYTES);
    dim3 grid(NTQ, B_ * H_);
    attn_mma<<<grid, 256, SMEM_BYTES>>>(Q, K, V, outV, outA);
}

// round 7
// speedup vs baseline: 1.8051x; 1.0006x over previous
#include <cuda_runtime.h>
#include <cuda_bf16.h>
#include <math.h>
#include <stdint.h>

namespace {

constexpr int B_  = 4;
constexpr int L_  = 2048;
constexpr int H_  = 16;
constexpr int E_  = 64;
constexpr int D_  = 64;
constexpr int TM  = 128;
constexpr int TN  = 128;
constexpr int NTQ = L_ / TM;            // 16
constexpr int RS  = H_ * E_;            // 1024
constexpr float QSCALE = 0.125f * 1.4426950408889634f;   // 1/sqrt(64) * log2(e)
constexpr size_t V_ELEMS = (size_t)B_ * L_ * H_ * D_;

// smem byte offsets
constexpr int QH_OFF = 0;        // [128][64] bf16 planes, 128B rows, XOR swizzle
constexpr int QL_OFF = 16384;
constexpr int KH_OFF = 32768;
constexpr int KL_OFF = 49152;
constexpr int VH_OFF = 65536;
constexpr int VL_OFF = 81920;
constexpr int FK_OFF = 98304;    // fp32 staging K tile [128][64]
constexpr int FV_OFF = 131072;   // fp32 staging V tile
constexpr int SMEM_BYTES = 163840;   // 160 KB

__device__ __forceinline__ void ldsm4(uint32_t r[4], uint32_t a) {
    asm volatile("ldmatrix.sync.aligned.m8n8.x4.shared.b16 {%0,%1,%2,%3}, [%4];"
        : "=r"(r[0]), "=r"(r[1]), "=r"(r[2]), "=r"(r[3]) : "r"(a));
}
__device__ __forceinline__ void ldsm4t(uint32_t r[4], uint32_t a) {
    asm volatile("ldmatrix.sync.aligned.m8n8.x4.trans.shared.b16 {%0,%1,%2,%3}, [%4];"
        : "=r"(r[0]), "=r"(r[1]), "=r"(r[2]), "=r"(r[3]) : "r"(a));
}
__device__ __forceinline__ void mma_bf16(float c[4], const uint32_t a[4],
                                         uint32_t b0, uint32_t b1) {
    asm volatile(
        "mma.sync.aligned.m16n8k16.row.col.f32.bf16.bf16.f32 "
        "{%0,%1,%2,%3}, {%4,%5,%6,%7}, {%8,%9}, {%0,%1,%2,%3};"
        : "+f"(c[0]), "+f"(c[1]), "+f"(c[2]), "+f"(c[3])
        : "r"(a[0]), "r"(a[1]), "r"(a[2]), "r"(a[3]), "r"(b0), "r"(b1));
}
__device__ __forceinline__ float ex2(float x) {
    float y;
    asm("ex2.approx.ftz.f32 %0, %1;" : "=f"(y) : "f"(x));
    return y;
}
__device__ __forceinline__ void cp16(uint32_t dst, const void* src) {
    asm volatile("cp.async.cg.shared.global [%0], [%1], 16;" :: "r"(dst), "l"(src));
}
__device__ __forceinline__ void cp_commit() {
    asm volatile("cp.async.commit_group;");
}
template <int N>
__device__ __forceinline__ void cp_wait() {
    asm volatile("cp.async.wait_group %0;" :: "n"(N));
}

__device__ __forceinline__ uint32_t pack2(float x, float y) {
    uint16_t hx = __bfloat16_as_ushort(__float2bfloat16_rn(x));
    uint16_t hy = __bfloat16_as_ushort(__float2bfloat16_rn(y));
    return (uint32_t)hx | ((uint32_t)hy << 16);
}
__device__ __forceinline__ void split2(float x, float y, uint32_t& hi, uint32_t& lo) {
    __nv_bfloat16 xh = __float2bfloat16_rn(x);
    __nv_bfloat16 yh = __float2bfloat16_rn(y);
    hi = (uint32_t)__bfloat16_as_ushort(xh) | ((uint32_t)__bfloat16_as_ushort(yh) << 16);
    lo = pack2(x - __bfloat162float(xh), y - __bfloat162float(yh));
}

// stage 128x64 fp32 tile from GLOBAL into hi/lo bf16 planes (for Q only)
__device__ __forceinline__ void stage_hl(const float* __restrict__ g,
                                         char* sm, int HOFF, int LOFF,
                                         int tid, float scale) {
    #pragma unroll
    for (int it = 0; it < 8; ++it) {
        int idx = it * 256 + tid;
        int n  = idx >> 4;
        int e4 = (idx & 15) << 2;
        float4 v = *(const float4*)(g + (size_t)n * RS + e4);
        v.x *= scale; v.y *= scale; v.z *= scale; v.w *= scale;
        uint32_t h0, l0, h1, l1;
        split2(v.x, v.y, h0, l0);
        split2(v.z, v.w, h1, l1);
        int ch  = (e4 >> 3) ^ (n & 7);
        int off = n * 128 + ch * 16 + (e4 & 4) * 2;
        *(uint2*)(sm + HOFF + off) = make_uint2(h0, h1);
        *(uint2*)(sm + LOFF + off) = make_uint2(l0, l1);
    }
}

// async prefetch: global fp32 tile -> smem staging buffer
__device__ __forceinline__ void prefetch_tile(const float* __restrict__ g,
                                              uint32_t dstb, int tid) {
    #pragma unroll
    for (int it = 0; it < 8; ++it) {
        int idx = it * 256 + tid;
        int n  = idx >> 4;
        int e4 = (idx & 15) << 2;
        cp16(dstb + (uint32_t)(n * 256 + e4 * 4), g + (size_t)n * RS + e4);
    }
}

// convert fp32 staging -> hi + lo planes
__device__ __forceinline__ void convert_hl(const char* src, char* sm,
                                           int HOFF, int LOFF, int tid) {
    const float* f = (const float*)src;
    #pragma unroll
    for (int it = 0; it < 8; ++it) {
        int idx = it * 256 + tid;
        int n  = idx >> 4;
        int e4 = (idx & 15) << 2;
        float4 v = *(const float4*)(f + n * 64 + e4);
        uint32_t h0, l0, h1, l1;
        split2(v.x, v.y, h0, l0);
        split2(v.z, v.w, h1, l1);
        int ch  = (e4 >> 3) ^ (n & 7);
        int off = n * 128 + ch * 16 + (e4 & 4) * 2;
        *(uint2*)(sm + HOFF + off) = make_uint2(h0, h1);
        *(uint2*)(sm + LOFF + off) = make_uint2(l0, l1);
    }
}

// 3-term split S — MUST be the unique score function for both passes
// (pass-1 (m,l) and pass-2 normalization need bitwise-identical scores)
__device__ __forceinline__ void compute_S3(float acc[16][4],
                                           const uint32_t qh[4][4], const uint32_t ql[4][4],
                                           uint32_t khb, uint32_t klb, int lane) {
    #pragma unroll
    for (int nt = 0; nt < 16; ++nt) {
        const int row = nt * 8 + (lane & 7);
        const uint32_t roff = row * 128;
        uint32_t kh0[4], kh1[4], kl0[4], kl1[4];
        ldsm4(kh0, khb + roff + ((uint32_t)(((lane >> 3)    ) ^ (row & 7)) << 4));
        ldsm4(kh1, khb + roff + ((uint32_t)((4 + (lane >> 3)) ^ (row & 7)) << 4));
        ldsm4(kl0, klb + roff + ((uint32_t)(((lane >> 3)    ) ^ (row & 7)) << 4));
        ldsm4(kl1, klb + roff + ((uint32_t)((4 + (lane >> 3)) ^ (row & 7)) << 4));
        float* c = acc[nt];
        mma_bf16(c, qh[0], kh0[0], kh0[1]);
        mma_bf16(c, qh[1], kh0[2], kh0[3]);
        mma_bf16(c, qh[2], kh1[0], kh1[1]);
        mma_bf16(c, qh[3], kh1[2], kh1[3]);
        mma_bf16(c, ql[0], kh0[0], kh0[1]);
        mma_bf16(c, ql[1], kh0[2], kh0[3]);
        mma_bf16(c, ql[2], kh1[0], kh1[1]);
        mma_bf16(c, ql[3], kh1[2], kh1[3]);
        mma_bf16(c, qh[0], kl0[0], kl0[1]);
        mma_bf16(c, qh[1], kl0[2], kl0[3]);
        mma_bf16(c, qh[2], kl1[0], kl1[1]);
        mma_bf16(c, qh[3], kl1[2], kl1[3]);
    }
}

__device__ __forceinline__ void mask_diag(float acc[16][4], int jTN,
                                          int grow0, int grow1, int cq) {
    #pragma unroll
    for (int nt = 0; nt < 16; ++nt) {
        int c0g = jTN + nt * 8 + cq;
        if (c0g     > grow0) acc[nt][0] = -1e30f;
        if (c0g + 1 > grow0) acc[nt][1] = -1e30f;
        if (c0g     > grow1) acc[nt][2] = -1e30f;
        if (c0g + 1 > grow1) acc[nt][3] = -1e30f;
    }
}

__global__ void __launch_bounds__(256, 1)
attn_mma(const float* __restrict__ Q, const float* __restrict__ K,
         const float* __restrict__ Vv, float* __restrict__ outV,
         float* __restrict__ outA)
{
    extern __shared__ char sm[];
    const int qt  = (NTQ - 1) - blockIdx.x;     // heavy tiles first
    const int bh  = blockIdx.y;
    const int b   = bh >> 4;
    const int h   = bh & 15;
    const int tid = threadIdx.x;
    const int wid = tid >> 5;
    const int lane = tid & 31;
    const int m0  = wid * 16;
    const int rq  = lane >> 2;
    const int cq  = (lane & 3) * 2;

    const uint32_t smb = (uint32_t)__cvta_generic_to_shared(sm);
    const float* Kbase = K  + ((size_t)(b * L_) * H_ + h) * E_;
    const float* Vbase = Vv + ((size_t)(b * L_) * H_ + h) * D_;

    // stage Q (pre-scaled into log2 domain), kick K tile-0 prefetch
    stage_hl(Q + ((size_t)(b * L_ + qt * TM) * H_ + h) * E_, sm, QH_OFF, QL_OFF, tid, QSCALE);
    prefetch_tile(Kbase, smb + FK_OFF, tid);
    cp_commit();
    __syncthreads();

    // persistent Q fragments (hi + lo)
    uint32_t qh[4][4], ql[4][4];
    #pragma unroll
    for (int ks = 0; ks < 4; ++ks) {
        int row = m0 + (lane & 7) + ((lane >> 3) & 1) * 8;
        int ch  = 2 * ks + (lane >> 4);
        uint32_t off = row * 128 + ((uint32_t)(ch ^ (row & 7)) << 4);
        ldsm4(qh[ks], smb + QH_OFF + off);
        ldsm4(ql[ks], smb + QL_OFF + off);
    }

    const int grow0 = qt * TM + m0 + rq;
    const int grow1 = grow0 + 8;

    float m_run[2] = {-1e30f, -1e30f};
    float l_run[2] = {0.0f, 0.0f};

    // =================== pass 1: stats only (3-term, identical to pass 2) ===================
    for (int j = 0; j <= qt; ++j) {
        cp_wait<0>();
        __syncthreads();                      // staging arrived; KH/KL free
        convert_hl(sm + FK_OFF, sm, KH_OFF, KL_OFF, tid);
        __syncthreads();                      // KH/KL ready; staging free
        if (j < qt) {
            prefetch_tile(Kbase + (size_t)(j + 1) * TN * RS, smb + FK_OFF, tid);
            cp_commit();
        }

        float acc[16][4];
        #pragma unroll
        for (int nt = 0; nt < 16; ++nt)
            #pragma unroll
            for (int e = 0; e < 4; ++e) acc[nt][e] = 0.0f;

        compute_S3(acc, qh, ql, smb + KH_OFF, smb + KL_OFF, lane);
        if (j == qt) mask_diag(acc, j * TN, grow0, grow1, cq);

        float mx0 = -1e30f, mx1 = -1e30f;
        #pragma unroll
        for (int nt = 0; nt < 16; ++nt) {
            mx0 = fmaxf(mx0, fmaxf(acc[nt][0], acc[nt][1]));
            mx1 = fmaxf(mx1, fmaxf(acc[nt][2], acc[nt][3]));
        }
        mx0 = fmaxf(mx0, __shfl_xor_sync(0xffffffffu, mx0, 1));
        mx0 = fmaxf(mx0, __shfl_xor_sync(0xffffffffu, mx0, 2));
        mx1 = fmaxf(mx1, __shfl_xor_sync(0xffffffffu, mx1, 1));
        mx1 = fmaxf(mx1, __shfl_xor_sync(0xffffffffu, mx1, 2));
        float mn0 = fmaxf(m_run[0], mx0);
        float mn1 = fmaxf(m_run[1], mx1);
        float s0 = 0.0f, s1 = 0.0f;
        #pragma unroll
        for (int nt = 0; nt < 16; ++nt) {
            s0 += ex2(acc[nt][0] - mn0) + ex2(acc[nt][1] - mn0);
            s1 += ex2(acc[nt][2] - mn1) + ex2(acc[nt][3] - mn1);
        }
        s0 += __shfl_xor_sync(0xffffffffu, s0, 1);
        s0 += __shfl_xor_sync(0xffffffffu, s0, 2);
        s1 += __shfl_xor_sync(0xffffffffu, s1, 1);
        s1 += __shfl_xor_sync(0xffffffffu, s1, 2);
        l_run[0] = l_run[0] * ex2(m_run[0] - mn0) + s0;  m_run[0] = mn0;
        l_run[1] = l_run[1] * ex2(m_run[1] - mn1) + s1;  m_run[1] = mn1;
    }
    const float inv_l0 = 1.0f / l_run[0];
    const float inv_l1 = 1.0f / l_run[1];

    // prefetch pass-2 tile 0 (K and V) — overlaps with zero-fill below
    prefetch_tile(Kbase, smb + FK_OFF, tid);
    prefetch_tile(Vbase, smb + FV_OFF, tid);
    cp_commit();

    // =================== zero strictly-upper tiles of A ===================
    float* aBase = outA + ((size_t)bh * L_ + (size_t)qt * TM) * L_;
    for (int j = qt + 1; j < NTQ; ++j) {
        #pragma unroll
        for (int it = 0; it < 16; ++it) {
            int idx = it * 256 + tid;
            int r   = idx >> 5;
            int c4  = (idx & 31) << 2;
            *(float4*)(aBase + (size_t)r * L_ + j * TN + c4) = make_float4(0.f, 0.f, 0.f, 0.f);
        }
    }

    // =================== pass 2: recompute (3-term), write A, PV ===================
    float o[8][4];
    #pragma unroll
    for (int dt = 0; dt < 8; ++dt)
        #pragma unroll
        for (int e = 0; e < 4; ++e) o[dt][e] = 0.0f;

    for (int j = 0; j <= qt; ++j) {
        cp_wait<0>();
        __syncthreads();
        convert_hl(sm + FK_OFF, sm, KH_OFF, KL_OFF, tid);
        convert_hl(sm + FV_OFF, sm, VH_OFF, VL_OFF, tid);
        __syncthreads();
        if (j < qt) {
            prefetch_tile(Kbase + (size_t)(j + 1) * TN * RS, smb + FK_OFF, tid);
            prefetch_tile(Vbase + (size_t)(j + 1) * TN * RS, smb + FV_OFF, tid);
            cp_commit();
        }

        float acc[16][4];
        #pragma unroll
        for (int nt = 0; nt < 16; ++nt)
            #pragma unroll
            for (int e = 0; e < 4; ++e) acc[nt][e] = 0.0f;

        compute_S3(acc, qh, ql, smb + KH_OFF, smb + KL_OFF, lane);
        if (j == qt) mask_diag(acc, j * TN, grow0, grow1, cq);

        // fused per-quarter: normalize -> write A -> split -> PV MMAs
        // (P fragments live only 16 regs at a time)
        const int r_lo = m0 + rq;
        #pragma unroll
        for (int q4 = 0; q4 < 4; ++q4) {
            uint32_t ph[2][4], pl[2][4];
            #pragma unroll
            for (int t = 0; t < 4; ++t) {
                const int nt = 4 * q4 + t;
                float p00 = ex2(acc[nt][0] - m_run[0]) * inv_l0;
                float p01 = ex2(acc[nt][1] - m_run[0]) * inv_l0;
                float p10 = ex2(acc[nt][2] - m_run[1]) * inv_l1;
                float p11 = ex2(acc[nt][3] - m_run[1]) * inv_l1;
                int c = nt * 8 + cq;
                float* a0p = aBase + (size_t)r_lo * L_ + j * TN + c;
                *(float2*)a0p            = make_float2(p00, p01);
                *(float2*)(a0p + 8 * L_) = make_float2(p10, p11);
                const int kc = t >> 1;
                const int hf = (t & 1) * 2;
                split2(p00, p01, ph[kc][hf],     pl[kc][hf]);
                split2(p10, p11, ph[kc][hf + 1], pl[kc][hf + 1]);
            }
            const int row = q4 * 32 + lane;
            #pragma unroll
            for (int dt = 0; dt < 8; ++dt) {
                uint32_t off = row * 128 + ((uint32_t)(dt ^ (row & 7)) << 4);
                uint32_t vh[4], vl[4];
                ldsm4t(vh, smb + VH_OFF + off);
                ldsm4t(vl, smb + VL_OFF + off);
                mma_bf16(o[dt], ph[0], vh[0], vh[1]);
                mma_bf16(o[dt], ph[1], vh[2], vh[3]);
                mma_bf16(o[dt], ph[0], vl[0], vl[1]);
                mma_bf16(o[dt], ph[1], vl[2], vl[3]);
                mma_bf16(o[dt], pl[0], vh[0], vh[1]);
                mma_bf16(o[dt], pl[1], vh[2], vh[3]);
            }
        }
    }

    // ---- write V output [B, L, H, D] ----
    float* vout = outV + ((size_t)(b * L_ + qt * TM) * H_ + h) * D_;
    #pragma unroll
    for (int dt = 0; dt < 8; ++dt) {
        int d = dt * 8 + cq;
        float* p0 = vout + (size_t)(m0 + rq) * RS + d;
        *(float2*)p0            = make_float2(o[dt][0], o[dt][1]);
        *(float2*)(p0 + 8 * RS) = make_float2(o[dt][2], o[dt][3]);
    }
}

} // namespace

extern "C" void kernel_launch(void* const* d_in, const int* in_sizes, int n_in,
                              void* d_out, int out_size)
{
    const float* Q = (const float*)d_in[0];
    const float* K = (const float*)d_in[1];
    const float* V = (const float*)d_in[2];
    float* outV = (float*)d_out;
    float* outA = outV + V_ELEMS;

    cudaFuncSetAttribute(attn_mma, cudaFuncAttributeMaxDynamicSharedMemorySize, SMEM_BYTES);
    dim3 grid(NTQ, B_ * H_);
    attn_mma<<<grid, 256, SMEM_BYTES>>>(Q, K, V, outV, outA);
}